// round 2
// baseline (speedup 1.0000x reference)
#include <cuda_runtime.h>
#include <math.h>

// Problem constants
#define BB 2
#define TT 2048
#define DM 1024
#define NH 16
#define HD 64
#define MROWS (BB*TT)     // 4096
#define KBAND 256

// ---------------- scratch (device globals; no allocation allowed) ----------------
__device__ float g_Q[MROWS*DM];
__device__ float g_K[MROWS*DM];
__device__ float g_V[MROWS*DM];
__device__ float g_O[MROWS*DM];

// ---------------- tf32 helpers ----------------
__device__ __forceinline__ unsigned cvt_tf32(float f){
    unsigned u; asm("cvt.rna.tf32.f32 %0, %1;" : "=r"(u) : "f"(f)); return u;
}
__device__ __forceinline__ void split_tf32(float f, unsigned &hi, unsigned &lo){
    hi = cvt_tf32(f);
    float r = f - __uint_as_float(hi);
    lo = cvt_tf32(r);
}
__device__ __forceinline__ void mma8(float c[4], const unsigned a[4], const unsigned b[2]){
    asm volatile(
      "mma.sync.aligned.m16n8k8.row.col.f32.tf32.tf32.f32 "
      "{%0,%1,%2,%3}, {%4,%5,%6,%7}, {%8,%9}, {%0,%1,%2,%3};"
      : "+f"(c[0]), "+f"(c[1]), "+f"(c[2]), "+f"(c[3])
      : "r"(a[0]), "r"(a[1]), "r"(a[2]), "r"(a[3]), "r"(b[0]), "r"(b[1]));
}

// ======================= GEMM: C[M,N] = A[M,K] @ W[K,N] + bias =======================
// 128x128 block, BK=32, 256 threads (8 warps, warp tile 32x64), 3xTF32 split accuracy.
__global__ void __launch_bounds__(256) gemm_bias_kernel(
    const float* __restrict__ A, const float* __restrict__ W,
    const float* __restrict__ bias, float* __restrict__ C,
    int M, int N, int K)
{
    __shared__ float As[128][36];   // pitch 36: frag addr = 4r + c mod 32 -> conflict free
    __shared__ float Bs[32][136];   // pitch 136: frag addr = 8k + n mod 32 -> conflict free

    const int tid  = threadIdx.x;
    const int warp = tid >> 5, lane = tid & 31;
    const int wm = warp >> 1;        // 0..3 (32 rows each)
    const int wn = warp & 1;         // 0..1 (64 cols each)
    const int bm = blockIdx.y * 128;
    const int bn = blockIdx.x * 128;

    float acc[2][8][4];
#pragma unroll
    for (int mt=0; mt<2; mt++)
#pragma unroll
      for (int nt=0; nt<8; nt++)
#pragma unroll
        for (int cc=0; cc<4; cc++) acc[mt][nt][cc] = 0.f;

    const int ar = tid >> 3;            // 0..31
    const int ac = (tid & 7) << 2;      // 0..28
    const int br = tid >> 5;            // 0..7
    const int bc = (tid & 31) << 2;     // 0..124

    for (int k0 = 0; k0 < K; k0 += 32){
#pragma unroll
        for (int i=0;i<4;i++){
            *(float4*)&As[ar + i*32][ac] =
                *(const float4*)&A[(size_t)(bm + ar + i*32)*K + k0 + ac];
            *(float4*)&Bs[br + i*8][bc]  =
                *(const float4*)&W[(size_t)(k0 + br + i*8)*N + bn + bc];
        }
        __syncthreads();

#pragma unroll
        for (int ks = 0; ks < 32; ks += 8){
            unsigned ah[2][4], al[2][4];
#pragma unroll
            for (int mt=0; mt<2; mt++){
                int r = wm*32 + mt*16 + (lane>>2);
                split_tf32(As[r  ][ks +     (lane&3)], ah[mt][0], al[mt][0]);
                split_tf32(As[r+8][ks +     (lane&3)], ah[mt][1], al[mt][1]);
                split_tf32(As[r  ][ks + 4 + (lane&3)], ah[mt][2], al[mt][2]);
                split_tf32(As[r+8][ks + 4 + (lane&3)], ah[mt][3], al[mt][3]);
            }
#pragma unroll
            for (int nt=0; nt<8; nt++){
                unsigned bh[2], bl[2];
                int ncol = wn*64 + nt*8 + (lane>>2);
                split_tf32(Bs[ks +     (lane&3)][ncol], bh[0], bl[0]);
                split_tf32(Bs[ks + 4 + (lane&3)][ncol], bh[1], bl[1]);
#pragma unroll
                for (int mt=0; mt<2; mt++){
                    mma8(acc[mt][nt], ah[mt], bh);
                    mma8(acc[mt][nt], ah[mt], bl);
                    mma8(acc[mt][nt], al[mt], bh);
                }
            }
        }
        __syncthreads();
    }

#pragma unroll
    for (int mt=0; mt<2; mt++){
#pragma unroll
        for (int nt=0; nt<8; nt++){
            int col = bn + wn*64 + nt*8 + ((lane&3)<<1);
            float b0 = bias[col], b1 = bias[col+1];
            int r0 = bm + wm*32 + mt*16 + (lane>>2);
            float2 v0 = make_float2(acc[mt][nt][0] + b0, acc[mt][nt][1] + b1);
            float2 v1 = make_float2(acc[mt][nt][2] + b0, acc[mt][nt][3] + b1);
            *(float2*)&C[(size_t)r0*N + col]     = v0;
            *(float2*)&C[(size_t)(r0+8)*N + col] = v1;
        }
    }
}

// ======================= Fused banded attention =======================
// grid: (T/64, B*H). Each block: 64 queries x 256 keys (blocks {qblk-1,qblk}).
// Computes S=QK^T (3xTF32), alibi+causal mask, softmax, writes P band to attn
// output (if present), then O = P @ V, written to g_O in (b,t)(h,d) layout.
#define QS_PITCH 68
#define KS_PITCH 76
#define PS_PITCH 260
#define SM_Q 0
#define SM_K (64*QS_PITCH)                    // 4352
#define SM_P (SM_K + 256*KS_PITCH)            // 4352+19456 = 23808
#define SMEM_FLOATS (SM_P + 64*PS_PITCH)      // 23808+16640 = 40448
#define SMEM_BYTES (SMEM_FLOATS*4)            // 161792

__global__ void __launch_bounds__(128) attn_kernel(float* __restrict__ attn_out, int has_attn)
{
    extern __shared__ float sm[];
    float* Qs = sm + SM_Q;
    float* Ks = sm + SM_K;   // reused for V in phase 2
    float* Ps = sm + SM_P;

    const int tid = threadIdx.x, warp = tid>>5, lane = tid&31;
    const int qtile = blockIdx.x;         // 0..31
    const int bh    = blockIdx.y;         // 0..31  (= b*NH + h)
    const int b = bh >> 4, h = bh & 15;
    const int qbase = qtile*64;
    const int qblk  = qbase >> 7;
    const int kstart = (qblk==0) ? 0 : (qblk-1)*128;

    // load Q tile: 64 rows x 64
#pragma unroll
    for (int i=0;i<8;i++){
        int idx = tid + i*128;
        int r = idx >> 4, c = (idx & 15) << 2;
        *(float4*)&Qs[r*QS_PITCH + c] =
            *(const float4*)&g_Q[((size_t)(b*TT + qbase + r))*DM + h*HD + c];
    }
    // load K tile: 256 rows x 64
#pragma unroll
    for (int i=0;i<32;i++){
        int idx = tid + i*128;
        int r = idx >> 4, c = (idx & 15) << 2;
        *(float4*)&Ks[r*KS_PITCH + c] =
            *(const float4*)&g_K[((size_t)(b*TT + kstart + r))*DM + h*HD + c];
    }
    __syncthreads();

    // -------- S = Q @ K^T : warp computes 16 rows x 256 cols --------
    float sc[32][4];
#pragma unroll
    for (int nt=0; nt<32; nt++)
#pragma unroll
        for (int cc=0; cc<4; cc++) sc[nt][cc] = 0.f;

    const int r0 = warp*16 + (lane>>2);
    for (int ks=0; ks<64; ks+=8){
        unsigned ah[4], al[4];
        split_tf32(Qs[ r0   *QS_PITCH + ks +     (lane&3)], ah[0], al[0]);
        split_tf32(Qs[(r0+8)*QS_PITCH + ks +     (lane&3)], ah[1], al[1]);
        split_tf32(Qs[ r0   *QS_PITCH + ks + 4 + (lane&3)], ah[2], al[2]);
        split_tf32(Qs[(r0+8)*QS_PITCH + ks + 4 + (lane&3)], ah[3], al[3]);
#pragma unroll
        for (int nt=0; nt<32; nt++){
            unsigned bhf[2], blf[2];
            int key = nt*8 + (lane>>2);
            split_tf32(Ks[key*KS_PITCH + ks +     (lane&3)], bhf[0], blf[0]);
            split_tf32(Ks[key*KS_PITCH + ks + 4 + (lane&3)], bhf[1], blf[1]);
            mma8(sc[nt], ah, bhf);
            mma8(sc[nt], ah, blf);
            mma8(sc[nt], al, bhf);
        }
    }

    // -------- alibi + causal mask + softmax (rows i0=r0, i1=r0+8) --------
    const float slope = exp2f(-0.5f*(float)(h+1));
    const int i0 = qbase + r0;
    const int i1 = i0 + 8;
    float m0 = -1e30f, m1 = -1e30f;
#pragma unroll
    for (int nt=0; nt<32; nt++){
        int j = kstart + nt*8 + ((lane&3)<<1);
        float s;
        s = sc[nt][0]*0.125f + slope*(float)(i0 - j);
        if (j   > i0) s = -1e30f; sc[nt][0]=s; m0=fmaxf(m0,s);
        s = sc[nt][1]*0.125f + slope*(float)(i0 - j - 1);
        if (j+1 > i0) s = -1e30f; sc[nt][1]=s; m0=fmaxf(m0,s);
        s = sc[nt][2]*0.125f + slope*(float)(i1 - j);
        if (j   > i1) s = -1e30f; sc[nt][2]=s; m1=fmaxf(m1,s);
        s = sc[nt][3]*0.125f + slope*(float)(i1 - j - 1);
        if (j+1 > i1) s = -1e30f; sc[nt][3]=s; m1=fmaxf(m1,s);
    }
    m0 = fmaxf(m0, __shfl_xor_sync(0xffffffffu, m0, 1));
    m0 = fmaxf(m0, __shfl_xor_sync(0xffffffffu, m0, 2));
    m1 = fmaxf(m1, __shfl_xor_sync(0xffffffffu, m1, 1));
    m1 = fmaxf(m1, __shfl_xor_sync(0xffffffffu, m1, 2));

    float l0 = 0.f, l1 = 0.f;
#pragma unroll
    for (int nt=0; nt<32; nt++){
        float p;
        p = expf(sc[nt][0]-m0); sc[nt][0]=p; l0+=p;
        p = expf(sc[nt][1]-m0); sc[nt][1]=p; l0+=p;
        p = expf(sc[nt][2]-m1); sc[nt][2]=p; l1+=p;
        p = expf(sc[nt][3]-m1); sc[nt][3]=p; l1+=p;
    }
    l0 += __shfl_xor_sync(0xffffffffu, l0, 1);
    l0 += __shfl_xor_sync(0xffffffffu, l0, 2);
    l1 += __shfl_xor_sync(0xffffffffu, l1, 1);
    l1 += __shfl_xor_sync(0xffffffffu, l1, 2);
    const float inv0 = 1.f/l0, inv1 = 1.f/l1;

#pragma unroll
    for (int nt=0; nt<32; nt++){
        int c = nt*8 + ((lane&3)<<1);
        Ps[(warp*16     + (lane>>2))*PS_PITCH + c    ] = sc[nt][0]*inv0;
        Ps[(warp*16     + (lane>>2))*PS_PITCH + c + 1] = sc[nt][1]*inv0;
        Ps[(warp*16 + 8 + (lane>>2))*PS_PITCH + c    ] = sc[nt][2]*inv1;
        Ps[(warp*16 + 8 + (lane>>2))*PS_PITCH + c + 1] = sc[nt][3]*inv1;
    }
    __syncthreads();

    // write probability band to attn output (coalesced), load V over K buffer
    if (has_attn){
#pragma unroll
        for (int i=0;i<32;i++){
            int idx = tid + i*128;
            int r = idx >> 6, c = (idx & 63) << 2;
            float4 v = *(float4*)&Ps[r*PS_PITCH + c];
            *(float4*)&attn_out[((size_t)bh*TT + qbase + r)*TT + kstart + c] = v;
        }
    }
#pragma unroll
    for (int i=0;i<32;i++){
        int idx = tid + i*128;
        int r = idx >> 4, c = (idx & 15) << 2;
        *(float4*)&Ks[r*KS_PITCH + c] =
            *(const float4*)&g_V[((size_t)(b*TT + kstart + r))*DM + h*HD + c];
    }
    __syncthreads();

    // -------- O = P @ V : warp computes 16 rows x 64 cols --------
    float oc[8][4];
#pragma unroll
    for (int nt=0; nt<8; nt++)
#pragma unroll
        for (int cc=0; cc<4; cc++) oc[nt][cc] = 0.f;

    for (int ks=0; ks<256; ks+=8){
        unsigned ah[4], al[4];
        split_tf32(Ps[ r0   *PS_PITCH + ks +     (lane&3)], ah[0], al[0]);
        split_tf32(Ps[(r0+8)*PS_PITCH + ks +     (lane&3)], ah[1], al[1]);
        split_tf32(Ps[ r0   *PS_PITCH + ks + 4 + (lane&3)], ah[2], al[2]);
        split_tf32(Ps[(r0+8)*PS_PITCH + ks + 4 + (lane&3)], ah[3], al[3]);
#pragma unroll
        for (int nt=0; nt<8; nt++){
            unsigned bhf[2], blf[2];
            int vk = ks + (lane&3);
            split_tf32(Ks[ vk   *KS_PITCH + nt*8 + (lane>>2)], bhf[0], blf[0]);
            split_tf32(Ks[(vk+4)*KS_PITCH + nt*8 + (lane>>2)], bhf[1], blf[1]);
            mma8(oc[nt], ah, bhf);
            mma8(oc[nt], ah, blf);
            mma8(oc[nt], al, bhf);
        }
    }

    // write O in (b*T+t, h*64+d) row-major layout
#pragma unroll
    for (int nt=0; nt<8; nt++){
        int col = h*HD + nt*8 + ((lane&3)<<1);
        size_t rg = (size_t)(b*TT + qbase + warp*16 + (lane>>2));
        *(float2*)&g_O[ rg     *DM + col] = make_float2(oc[nt][0], oc[nt][1]);
        *(float2*)&g_O[(rg + 8)*DM + col] = make_float2(oc[nt][2], oc[nt][3]);
    }
}

// ======================= host launcher =======================
extern "C" void kernel_launch(void* const* d_in, const int* in_sizes, int n_in,
                              void* d_out, int out_size)
{
    const float* x  = (const float*)d_in[0];
    const float* Wq = (const float*)d_in[1];
    const float* bq = (const float*)d_in[2];
    const float* Wk = (const float*)d_in[3];
    const float* bk = (const float*)d_in[4];
    const float* Wv = (const float*)d_in[5];
    const float* bv = (const float*)d_in[6];
    const float* Wo = (const float*)d_in[7];
    const float* bo = (const float*)d_in[8];
    float* out = (float*)d_out;

    const long long OUT_ELEMS  = (long long)MROWS*DM;        // 4,194,304
    const long long ATTN_ELEMS = (long long)BB*NH*TT*TT;     // 134,217,728
    const int has_attn = ((long long)out_size >= OUT_ELEMS + ATTN_ELEMS) ? 1 : 0;
    float* attn = has_attn ? (out + OUT_ELEMS) : nullptr;

    float *pQ, *pK, *pV, *pO;
    cudaGetSymbolAddress((void**)&pQ, g_Q);
    cudaGetSymbolAddress((void**)&pK, g_K);
    cudaGetSymbolAddress((void**)&pV, g_V);
    cudaGetSymbolAddress((void**)&pO, g_O);

    cudaFuncSetAttribute(attn_kernel, cudaFuncAttributeMaxDynamicSharedMemorySize, SMEM_BYTES);

    if (has_attn)
        cudaMemsetAsync(attn, 0, (size_t)ATTN_ELEMS * sizeof(float));

    dim3 gg(DM/128, MROWS/128);   // (8, 32)
    gemm_bias_kernel<<<gg, 256>>>(x, Wq, bq, pQ, MROWS, DM, DM);
    gemm_bias_kernel<<<gg, 256>>>(x, Wk, bk, pK, MROWS, DM, DM);
    gemm_bias_kernel<<<gg, 256>>>(x, Wv, bv, pV, MROWS, DM, DM);

    attn_kernel<<<dim3(TT/64, BB*NH), 128, SMEM_BYTES>>>(attn, has_attn);

    gemm_bias_kernel<<<gg, 256>>>(pO, Wo, bo, out, MROWS, DM, DM);
}

// round 3
// speedup vs baseline: 1.2541x; 1.2541x over previous
#include <cuda_runtime.h>
#include <math.h>

// Problem constants
#define BB 2
#define TT 2048
#define DM 1024
#define NH 16
#define HD 64
#define MROWS (BB*TT)     // 4096

// ---------------- scratch (device globals; no allocation allowed) ----------------
__device__ float g_Q[MROWS*DM];
__device__ float g_K[MROWS*DM];
__device__ float g_V[MROWS*DM];
__device__ float g_O[MROWS*DM];

// ---------------- tf32 helpers ----------------
__device__ __forceinline__ unsigned cvt_tf32(float f){
    unsigned u; asm("cvt.rna.tf32.f32 %0, %1;" : "=r"(u) : "f"(f)); return u;
}
__device__ __forceinline__ void split_tf32(float f, unsigned &hi, unsigned &lo){
    hi = cvt_tf32(f);
    float r = f - __uint_as_float(hi);
    lo = cvt_tf32(r);
}
__device__ __forceinline__ void split4(float4 v, float4 &h4, float4 &l4){
    unsigned h,l;
    split_tf32(v.x,h,l); h4.x=__uint_as_float(h); l4.x=__uint_as_float(l);
    split_tf32(v.y,h,l); h4.y=__uint_as_float(h); l4.y=__uint_as_float(l);
    split_tf32(v.z,h,l); h4.z=__uint_as_float(h); l4.z=__uint_as_float(l);
    split_tf32(v.w,h,l); h4.w=__uint_as_float(h); l4.w=__uint_as_float(l);
}
__device__ __forceinline__ void mma8(float c[4], const unsigned a[4], const unsigned b[2]){
    asm volatile(
      "mma.sync.aligned.m16n8k8.row.col.f32.tf32.tf32.f32 "
      "{%0,%1,%2,%3}, {%4,%5,%6,%7}, {%8,%9}, {%0,%1,%2,%3};"
      : "+f"(c[0]), "+f"(c[1]), "+f"(c[2]), "+f"(c[3])
      : "r"(a[0]), "r"(a[1]), "r"(a[2]), "r"(a[3]), "r"(b[0]), "r"(b[1]));
}
__device__ __forceinline__ unsigned fu(float f){ return __float_as_uint(f); }

// ======================= GEMM: C[M,N] = A[M,K] @ W[K,N] + bias =======================
// 128x128 tile, BK=32, 256 threads, hi/lo pre-split in smem, z selects (W,bias,C).
#define GA_PITCH 36
#define GB_PITCH 136
#define G_OFF_AH 0
#define G_OFF_AL (128*GA_PITCH)                 // 4608
#define G_OFF_BH (2*128*GA_PITCH)               // 9216
#define G_OFF_BL (G_OFF_BH + 32*GB_PITCH)       // 13568
#define G_SMEM_FLOATS (G_OFF_BL + 32*GB_PITCH)  // 17920
#define G_SMEM_BYTES (G_SMEM_FLOATS*4)          // 71680

__global__ void __launch_bounds__(256,2) gemm3_kernel(
    const float* __restrict__ A,
    const float* __restrict__ W0, const float* __restrict__ W1, const float* __restrict__ W2,
    const float* __restrict__ bb0, const float* __restrict__ bb1, const float* __restrict__ bb2,
    float* __restrict__ C0, float* __restrict__ C1, float* __restrict__ C2)
{
    extern __shared__ float gsm[];
    float* Ah = gsm + G_OFF_AH;
    float* Al = gsm + G_OFF_AL;
    float* Bh = gsm + G_OFF_BH;
    float* Bl = gsm + G_OFF_BL;

    const int z = blockIdx.z;
    const float* W    = (z==0) ? W0  : (z==1) ? W1  : W2;
    const float* bias = (z==0) ? bb0 : (z==1) ? bb1 : bb2;
    float*       C    = (z==0) ? C0  : (z==1) ? C1  : C2;

    const int tid  = threadIdx.x;
    const int warp = tid >> 5, lane = tid & 31;
    const int wm = warp >> 1;        // 0..3
    const int wn = warp & 1;         // 0..1
    const int bm = blockIdx.y * 128;
    const int bn = blockIdx.x * 128;

    float acc[2][8][4];
#pragma unroll
    for (int mt=0; mt<2; mt++)
#pragma unroll
      for (int nt=0; nt<8; nt++)
#pragma unroll
        for (int cc=0; cc<4; cc++) acc[mt][nt][cc] = 0.f;

    const int ar = tid >> 3;            // 0..31
    const int ac = (tid & 7) << 2;      // 0..28
    const int br = tid >> 5;            // 0..7
    const int bc = (tid & 31) << 2;     // 0..124
    const int la3 = lane & 3;
    const int lq  = lane >> 2;

    for (int k0 = 0; k0 < DM; k0 += 32){
#pragma unroll
        for (int i=0;i<4;i++){
            float4 va = *(const float4*)&A[(size_t)(bm + ar + i*32)*DM + k0 + ac];
            float4 vb = *(const float4*)&W[(size_t)(k0 + br + i*8)*DM + bn + bc];
            float4 h4,l4;
            split4(va,h4,l4);
            *(float4*)&Ah[(ar + i*32)*GA_PITCH + ac] = h4;
            *(float4*)&Al[(ar + i*32)*GA_PITCH + ac] = l4;
            split4(vb,h4,l4);
            *(float4*)&Bh[(br + i*8)*GB_PITCH + bc] = h4;
            *(float4*)&Bl[(br + i*8)*GB_PITCH + bc] = l4;
        }
        __syncthreads();

#pragma unroll
        for (int ks = 0; ks < 32; ks += 8){
            unsigned ah[2][4], al[2][4];
#pragma unroll
            for (int mt=0; mt<2; mt++){
                int r = wm*32 + mt*16 + lq;
                ah[mt][0] = fu(Ah[ r   *GA_PITCH + ks +     la3]);
                ah[mt][1] = fu(Ah[(r+8)*GA_PITCH + ks +     la3]);
                ah[mt][2] = fu(Ah[ r   *GA_PITCH + ks + 4 + la3]);
                ah[mt][3] = fu(Ah[(r+8)*GA_PITCH + ks + 4 + la3]);
                al[mt][0] = fu(Al[ r   *GA_PITCH + ks +     la3]);
                al[mt][1] = fu(Al[(r+8)*GA_PITCH + ks +     la3]);
                al[mt][2] = fu(Al[ r   *GA_PITCH + ks + 4 + la3]);
                al[mt][3] = fu(Al[(r+8)*GA_PITCH + ks + 4 + la3]);
            }
#pragma unroll
            for (int nt=0; nt<8; nt++){
                int ncol = wn*64 + nt*8 + lq;
                unsigned bhf[2], blf[2];
                bhf[0] = fu(Bh[(ks +     la3)*GB_PITCH + ncol]);
                bhf[1] = fu(Bh[(ks + 4 + la3)*GB_PITCH + ncol]);
                blf[0] = fu(Bl[(ks +     la3)*GB_PITCH + ncol]);
                blf[1] = fu(Bl[(ks + 4 + la3)*GB_PITCH + ncol]);
#pragma unroll
                for (int mt=0; mt<2; mt++){
                    mma8(acc[mt][nt], ah[mt], bhf);
                    mma8(acc[mt][nt], ah[mt], blf);
                    mma8(acc[mt][nt], al[mt], bhf);
                }
            }
        }
        __syncthreads();
    }

#pragma unroll
    for (int mt=0; mt<2; mt++){
#pragma unroll
        for (int nt=0; nt<8; nt++){
            int col = bn + wn*64 + nt*8 + (la3<<1);
            float b0 = bias[col], b1 = bias[col+1];
            int r0 = bm + wm*32 + mt*16 + lq;
            *(float2*)&C[(size_t)r0*DM + col]     = make_float2(acc[mt][nt][0] + b0, acc[mt][nt][1] + b1);
            *(float2*)&C[(size_t)(r0+8)*DM + col] = make_float2(acc[mt][nt][2] + b0, acc[mt][nt][3] + b1);
        }
    }
}

// ======================= Fused banded attention =======================
// grid (T/64, B*H), 256 threads (8 warps). Warp = 16 q-rows x 128 keys in QK^T,
// 16 q-rows x 32 d-cols in P@V. Q/K/V pre-split hi/lo in smem; P aliases Q region,
// V aliases K region. Writes FULL 2048-wide attn rows (band + zeros): no memset.
#define AQ_PITCH 68
#define AK_PITCH 68
#define AV_PITCH 72
#define AP_PITCH 260
#define A_OFF_QH 0
#define A_OFF_QL 4352
#define A_OFF_P  0                       // 64*260 = 16640 floats, overlaps Q
#define A_OFF_KH 16640
#define A_OFF_KL 35072                   // KH slot sized for V pitch (256*72=18432)
#define A_OFF_VH 16640
#define A_OFF_VL 35072
#define A_OFF_RM 53504                   // 128 floats: per-row max partials [64][2]
#define A_OFF_RS 53632                   // 128 floats: per-row sum partials
#define A_SMEM_FLOATS 53760
#define A_SMEM_BYTES (A_SMEM_FLOATS*4)   // 215040

__global__ void __launch_bounds__(256) attn_kernel(float* __restrict__ attn_out, int has_attn)
{
    extern __shared__ float sm[];
    float* Qh = sm + A_OFF_QH;
    float* Ql = sm + A_OFF_QL;
    float* Kh = sm + A_OFF_KH;
    float* Kl = sm + A_OFF_KL;
    float* Vh = sm + A_OFF_VH;
    float* Vl = sm + A_OFF_VL;
    float* Ps = sm + A_OFF_P;
    float* Rm = sm + A_OFF_RM;
    float* Rs = sm + A_OFF_RS;

    const int tid = threadIdx.x, warp = tid>>5, lane = tid&31;
    const int wm = warp >> 1;        // 0..3 (16 rows each)
    const int wn = warp & 1;         // 0..1 (128 keys / 32 d-cols each)
    const int la3 = lane & 3;
    const int lq  = lane >> 2;
    const int bh = blockIdx.y;
    const int b = bh >> 4, h = bh & 15;
    const int qbase = blockIdx.x * 64;
    const int qblk  = qbase >> 7;
    const int kstart = (qblk==0) ? 0 : (qblk-1)*128;

    // ---- load Q (64x64) and K (256x64), pre-split ----
#pragma unroll
    for (int i=0;i<4;i++){
        int idx = tid + i*256;
        int r = idx >> 4, c = (idx & 15) << 2;
        float4 v = *(const float4*)&g_Q[((size_t)(b*TT + qbase + r))*DM + h*HD + c];
        float4 h4,l4; split4(v,h4,l4);
        *(float4*)&Qh[r*AQ_PITCH + c] = h4;
        *(float4*)&Ql[r*AQ_PITCH + c] = l4;
    }
#pragma unroll
    for (int i=0;i<16;i++){
        int idx = tid + i*256;
        int r = idx >> 4, c = (idx & 15) << 2;
        float4 v = *(const float4*)&g_K[((size_t)(b*TT + kstart + r))*DM + h*HD + c];
        float4 h4,l4; split4(v,h4,l4);
        *(float4*)&Kh[r*AK_PITCH + c] = h4;
        *(float4*)&Kl[r*AK_PITCH + c] = l4;
    }
    __syncthreads();

    // ---- S = Q K^T : warp tile 16 rows x 128 keys ----
    const int rloc0 = wm*16 + lq;
    const int rloc1 = rloc0 + 8;
    float sc[16][4];
#pragma unroll
    for (int nt=0; nt<16; nt++)
#pragma unroll
        for (int cc=0; cc<4; cc++) sc[nt][cc] = 0.f;

#pragma unroll
    for (int ks=0; ks<64; ks+=8){
        unsigned ah[4], al[4];
        ah[0] = fu(Qh[rloc0*AQ_PITCH + ks +     la3]);
        ah[1] = fu(Qh[rloc1*AQ_PITCH + ks +     la3]);
        ah[2] = fu(Qh[rloc0*AQ_PITCH + ks + 4 + la3]);
        ah[3] = fu(Qh[rloc1*AQ_PITCH + ks + 4 + la3]);
        al[0] = fu(Ql[rloc0*AQ_PITCH + ks +     la3]);
        al[1] = fu(Ql[rloc1*AQ_PITCH + ks +     la3]);
        al[2] = fu(Ql[rloc0*AQ_PITCH + ks + 4 + la3]);
        al[3] = fu(Ql[rloc1*AQ_PITCH + ks + 4 + la3]);
#pragma unroll
        for (int nt=0; nt<16; nt++){
            int key = wn*128 + nt*8 + lq;
            unsigned bhf[2], blf[2];
            bhf[0] = fu(Kh[key*AK_PITCH + ks +     la3]);
            bhf[1] = fu(Kh[key*AK_PITCH + ks + 4 + la3]);
            blf[0] = fu(Kl[key*AK_PITCH + ks +     la3]);
            blf[1] = fu(Kl[key*AK_PITCH + ks + 4 + la3]);
            mma8(sc[nt], ah, bhf);
            mma8(sc[nt], ah, blf);
            mma8(sc[nt], al, bhf);
        }
    }

    // ---- alibi + causal mask, cross-warp softmax ----
    const float slope = exp2f(-0.5f*(float)(h+1));
    const int i0 = qbase + rloc0;
    const int i1 = i0 + 8;
    float m0 = -1e30f, m1 = -1e30f;
#pragma unroll
    for (int nt=0; nt<16; nt++){
        int j = kstart + wn*128 + nt*8 + (la3<<1);
        float s;
        s = sc[nt][0]*0.125f + slope*(float)(i0 - j);
        if (j   > i0) s = -1e30f; sc[nt][0]=s; m0=fmaxf(m0,s);
        s = sc[nt][1]*0.125f + slope*(float)(i0 - j - 1);
        if (j+1 > i0) s = -1e30f; sc[nt][1]=s; m0=fmaxf(m0,s);
        s = sc[nt][2]*0.125f + slope*(float)(i1 - j);
        if (j   > i1) s = -1e30f; sc[nt][2]=s; m1=fmaxf(m1,s);
        s = sc[nt][3]*0.125f + slope*(float)(i1 - j - 1);
        if (j+1 > i1) s = -1e30f; sc[nt][3]=s; m1=fmaxf(m1,s);
    }
    m0 = fmaxf(m0, __shfl_xor_sync(0xffffffffu, m0, 1));
    m0 = fmaxf(m0, __shfl_xor_sync(0xffffffffu, m0, 2));
    m1 = fmaxf(m1, __shfl_xor_sync(0xffffffffu, m1, 1));
    m1 = fmaxf(m1, __shfl_xor_sync(0xffffffffu, m1, 2));
    if (la3 == 0){
        Rm[rloc0*2 + wn] = m0;
        Rm[rloc1*2 + wn] = m1;
    }
    __syncthreads();
    m0 = fmaxf(Rm[rloc0*2], Rm[rloc0*2 + 1]);
    m1 = fmaxf(Rm[rloc1*2], Rm[rloc1*2 + 1]);

    float l0 = 0.f, l1 = 0.f;
#pragma unroll
    for (int nt=0; nt<16; nt++){
        float p;
        p = __expf(sc[nt][0]-m0); sc[nt][0]=p; l0+=p;
        p = __expf(sc[nt][1]-m0); sc[nt][1]=p; l0+=p;
        p = __expf(sc[nt][2]-m1); sc[nt][2]=p; l1+=p;
        p = __expf(sc[nt][3]-m1); sc[nt][3]=p; l1+=p;
    }
    l0 += __shfl_xor_sync(0xffffffffu, l0, 1);
    l0 += __shfl_xor_sync(0xffffffffu, l0, 2);
    l1 += __shfl_xor_sync(0xffffffffu, l1, 1);
    l1 += __shfl_xor_sync(0xffffffffu, l1, 2);
    if (la3 == 0){
        Rs[rloc0*2 + wn] = l0;
        Rs[rloc1*2 + wn] = l1;
    }
    __syncthreads();   // also: all Q reads done; P may overwrite Q region now
    const float inv0 = 1.f / (Rs[rloc0*2] + Rs[rloc0*2 + 1]);
    const float inv1 = 1.f / (Rs[rloc1*2] + Rs[rloc1*2 + 1]);

#pragma unroll
    for (int nt=0; nt<16; nt++){
        int c = wn*128 + nt*8 + (la3<<1);
        Ps[rloc0*AP_PITCH + c    ] = sc[nt][0]*inv0;
        Ps[rloc0*AP_PITCH + c + 1] = sc[nt][1]*inv0;
        Ps[rloc1*AP_PITCH + c    ] = sc[nt][2]*inv1;
        Ps[rloc1*AP_PITCH + c + 1] = sc[nt][3]*inv1;
    }
    __syncthreads();

    // ---- write full attn rows (band=P, rest=0); load V (pre-split, over K) ----
    if (has_attn){
        const float4 zero4 = make_float4(0.f,0.f,0.f,0.f);
#pragma unroll 4
        for (int i=0;i<128;i++){
            int idx = tid + i*256;             // 0..32767 (64 rows x 512 float4)
            int r = idx >> 9;
            int c = (idx & 511) << 2;
            int cc = c - kstart;
            float4 v = (cc >= 0 && cc < 256) ? *(float4*)&Ps[r*AP_PITCH + cc] : zero4;
            *(float4*)&attn_out[((size_t)bh*TT + qbase + r)*TT + c] = v;
        }
    }
#pragma unroll
    for (int i=0;i<16;i++){
        int idx = tid + i*256;
        int r = idx >> 4, c = (idx & 15) << 2;
        float4 v = *(const float4*)&g_V[((size_t)(b*TT + kstart + r))*DM + h*HD + c];
        float4 h4,l4; split4(v,h4,l4);
        *(float4*)&Vh[r*AV_PITCH + c] = h4;
        *(float4*)&Vl[r*AV_PITCH + c] = l4;
    }
    __syncthreads();

    // ---- O = P @ V : warp tile 16 rows x 32 cols ----
    float oc[4][4];
#pragma unroll
    for (int nt=0; nt<4; nt++)
#pragma unroll
        for (int cc=0; cc<4; cc++) oc[nt][cc] = 0.f;

    for (int ks=0; ks<256; ks+=8){
        unsigned ah[4], al[4];
        split_tf32(Ps[rloc0*AP_PITCH + ks +     la3], ah[0], al[0]);
        split_tf32(Ps[rloc1*AP_PITCH + ks +     la3], ah[1], al[1]);
        split_tf32(Ps[rloc0*AP_PITCH + ks + 4 + la3], ah[2], al[2]);
        split_tf32(Ps[rloc1*AP_PITCH + ks + 4 + la3], ah[3], al[3]);
#pragma unroll
        for (int nt=0; nt<4; nt++){
            int n = wn*32 + nt*8 + lq;
            unsigned bhf[2], blf[2];
            bhf[0] = fu(Vh[(ks +     la3)*AV_PITCH + n]);
            bhf[1] = fu(Vh[(ks + 4 + la3)*AV_PITCH + n]);
            blf[0] = fu(Vl[(ks +     la3)*AV_PITCH + n]);
            blf[1] = fu(Vl[(ks + 4 + la3)*AV_PITCH + n]);
            mma8(oc[nt], ah, bhf);
            mma8(oc[nt], ah, blf);
            mma8(oc[nt], al, bhf);
        }
    }

    // ---- write O in (b*T+t, h*64+d) layout ----
#pragma unroll
    for (int nt=0; nt<4; nt++){
        int col = h*HD + wn*32 + nt*8 + (la3<<1);
        size_t rg = (size_t)(b*TT + qbase + rloc0);
        *(float2*)&g_O[ rg     *DM + col] = make_float2(oc[nt][0], oc[nt][1]);
        *(float2*)&g_O[(rg + 8)*DM + col] = make_float2(oc[nt][2], oc[nt][3]);
    }
}

// ======================= host launcher =======================
extern "C" void kernel_launch(void* const* d_in, const int* in_sizes, int n_in,
                              void* d_out, int out_size)
{
    const float* x  = (const float*)d_in[0];
    const float* Wq = (const float*)d_in[1];
    const float* bq = (const float*)d_in[2];
    const float* Wk = (const float*)d_in[3];
    const float* bk = (const float*)d_in[4];
    const float* Wv = (const float*)d_in[5];
    const float* bv = (const float*)d_in[6];
    const float* Wo = (const float*)d_in[7];
    const float* bo = (const float*)d_in[8];
    float* out = (float*)d_out;

    const long long OUT_ELEMS  = (long long)MROWS*DM;        // 4,194,304
    const long long ATTN_ELEMS = (long long)BB*NH*TT*TT;     // 134,217,728
    const int has_attn = ((long long)out_size >= OUT_ELEMS + ATTN_ELEMS) ? 1 : 0;
    float* attn = has_attn ? (out + OUT_ELEMS) : nullptr;

    float *pQ, *pK, *pV, *pO;
    cudaGetSymbolAddress((void**)&pQ, g_Q);
    cudaGetSymbolAddress((void**)&pK, g_K);
    cudaGetSymbolAddress((void**)&pV, g_V);
    cudaGetSymbolAddress((void**)&pO, g_O);

    static int attr_done = 0;
    if (!attr_done){
        cudaFuncSetAttribute(gemm3_kernel, cudaFuncAttributeMaxDynamicSharedMemorySize, G_SMEM_BYTES);
        cudaFuncSetAttribute(attn_kernel,  cudaFuncAttributeMaxDynamicSharedMemorySize, A_SMEM_BYTES);
        attr_done = 1;
    }

    // fused Q/K/V projections
    gemm3_kernel<<<dim3(DM/128, MROWS/128, 3), 256, G_SMEM_BYTES>>>(
        x, Wq, Wk, Wv, bq, bk, bv, pQ, pK, pV);

    // banded attention (writes full attn rows: band + zeros)
    attn_kernel<<<dim3(TT/64, BB*NH), 256, A_SMEM_BYTES>>>(attn, has_attn);

    // output projection
    gemm3_kernel<<<dim3(DM/128, MROWS/128, 1), 256, G_SMEM_BYTES>>>(
        pO, Wo, Wo, Wo, bo, bo, bo, out, out, out);
}

// round 4
// speedup vs baseline: 2.0738x; 1.6536x over previous
#include <cuda_runtime.h>
#include <cuda_bf16.h>
#include <math.h>

// Problem constants
#define BB 2
#define TT 2048
#define DM 1024
#define NH 16
#define HD 64
#define MROWS (BB*TT)     // 4096

// ---------------- scratch (device globals; no allocation allowed) ----------------
__device__ float g_Q[MROWS*DM];
__device__ float g_K[MROWS*DM];
__device__ float g_V[MROWS*DM];
__device__ float g_O[MROWS*DM];

// ---------------- bf16 split helpers ----------------
// split x into hi=bf16(x), lo=bf16(x-hi); packs (x,y) pairs into bf16x2 words.
__device__ __forceinline__ void split_bf2(float x, float y, unsigned &h, unsigned &l){
    __nv_bfloat162 hh = __floats2bfloat162_rn(x, y);
    float2 hf = __bfloat1622float2(hh);
    __nv_bfloat162 ll = __floats2bfloat162_rn(x - hf.x, y - hf.y);
    h = *(unsigned*)&hh;
    l = *(unsigned*)&ll;
}

__device__ __forceinline__ unsigned smaddr(const void* p){
    return (unsigned)__cvta_generic_to_shared(p);
}
__device__ __forceinline__ void ldsm_x4(unsigned &r0, unsigned &r1, unsigned &r2, unsigned &r3, unsigned a){
    asm volatile("ldmatrix.sync.aligned.m8n8.x4.shared.b16 {%0,%1,%2,%3}, [%4];"
        : "=r"(r0),"=r"(r1),"=r"(r2),"=r"(r3) : "r"(a));
}
__device__ __forceinline__ void ldsm_x4t(unsigned &r0, unsigned &r1, unsigned &r2, unsigned &r3, unsigned a){
    asm volatile("ldmatrix.sync.aligned.m8n8.x4.trans.shared.b16 {%0,%1,%2,%3}, [%4];"
        : "=r"(r0),"=r"(r1),"=r"(r2),"=r"(r3) : "r"(a));
}
__device__ __forceinline__ void mma16816(float c[4], const unsigned a[4], unsigned b0, unsigned b1){
    asm volatile(
      "mma.sync.aligned.m16n8k16.row.col.f32.bf16.bf16.f32 "
      "{%0,%1,%2,%3}, {%4,%5,%6,%7}, {%8,%9}, {%0,%1,%2,%3};"
      : "+f"(c[0]), "+f"(c[1]), "+f"(c[2]), "+f"(c[3])
      : "r"(a[0]), "r"(a[1]), "r"(a[2]), "r"(a[3]), "r"(b0), "r"(b1));
}

// ======================= GEMM: C[M,N] = A[M,K] @ W[K,N] + bias (bf16x3) =======================
// 128x128 tile, BK=32, 256 threads (8 warps, warp tile 32x64). A/B pre-split to bf16 hi/lo in
// smem; fragments via ldmatrix (B via .trans so no smem transpose needed).
#define GAP 40    // As pitch (bf16 elems): 80B rows -> ldmatrix conflict-free
#define GBP 136   // Bs pitch (bf16 elems): 272B rows -> conflict-free

__global__ void __launch_bounds__(256,2) gemm3_kernel(
    const float* __restrict__ A,
    const float* __restrict__ W0, const float* __restrict__ W1, const float* __restrict__ W2,
    const float* __restrict__ bb0, const float* __restrict__ bb1, const float* __restrict__ bb2,
    float* __restrict__ C0, float* __restrict__ C1, float* __restrict__ C2)
{
    __shared__ __align__(16) unsigned short Ah[128*GAP];
    __shared__ __align__(16) unsigned short Al[128*GAP];
    __shared__ __align__(16) unsigned short Bh[32*GBP];
    __shared__ __align__(16) unsigned short Bl[32*GBP];

    const int z = blockIdx.z;
    const float* W    = (z==0) ? W0  : (z==1) ? W1  : W2;
    const float* bias = (z==0) ? bb0 : (z==1) ? bb1 : bb2;
    float*       C    = (z==0) ? C0  : (z==1) ? C1  : C2;

    const int tid  = threadIdx.x;
    const int warp = tid >> 5, lane = tid & 31;
    const int wm = warp >> 1;        // 0..3
    const int wn = warp & 1;         // 0..1
    const int bm = blockIdx.y * 128;
    const int bn = blockIdx.x * 128;

    float acc[2][8][4];
#pragma unroll
    for (int mt=0; mt<2; mt++)
#pragma unroll
      for (int nt=0; nt<8; nt++)
#pragma unroll
        for (int cc=0; cc<4; cc++) acc[mt][nt][cc] = 0.f;

    // loaders
    const int ar = tid >> 3;            // 0..31
    const int ac = (tid & 7) << 2;      // 0..28
    const int br = tid >> 5;            // 0..7
    const int bc = (tid & 31) << 2;     // 0..124

    // ldmatrix per-lane offsets
    const int a_r = lane & 15;
    const int a_c = (lane >> 4) << 3;          // 0 or 8
    const int b_k = (((lane >> 3) & 1) << 3) + (lane & 7);
    const int b_n = ((lane >> 4) & 1) << 3;    // 0 or 8

    const unsigned uAh = smaddr(Ah), uAl = smaddr(Al);
    const unsigned uBh = smaddr(Bh), uBl = smaddr(Bl);

    const int la3 = lane & 3, lq = lane >> 2;

    for (int k0 = 0; k0 < DM; k0 += 32){
#pragma unroll
        for (int i=0;i<4;i++){
            float4 va = *(const float4*)&A[(size_t)(bm + ar + i*32)*DM + k0 + ac];
            float4 vb = *(const float4*)&W[(size_t)(k0 + br + i*8)*DM + bn + bc];
            unsigned h0,l0,h1,l1;
            split_bf2(va.x, va.y, h0, l0);
            split_bf2(va.z, va.w, h1, l1);
            *(uint2*)&Ah[(ar + i*32)*GAP + ac] = make_uint2(h0,h1);
            *(uint2*)&Al[(ar + i*32)*GAP + ac] = make_uint2(l0,l1);
            split_bf2(vb.x, vb.y, h0, l0);
            split_bf2(vb.z, vb.w, h1, l1);
            *(uint2*)&Bh[(br + i*8)*GBP + bc] = make_uint2(h0,h1);
            *(uint2*)&Bl[(br + i*8)*GBP + bc] = make_uint2(l0,l1);
        }
        __syncthreads();

#pragma unroll
        for (int ks = 0; ks < 32; ks += 16){
            unsigned ahi[2][4], alo[2][4];
#pragma unroll
            for (int mt=0; mt<2; mt++){
                unsigned off = (unsigned)(((wm*32 + mt*16 + a_r)*GAP + ks + a_c)*2);
                ldsm_x4(ahi[mt][0],ahi[mt][1],ahi[mt][2],ahi[mt][3], uAh + off);
                ldsm_x4(alo[mt][0],alo[mt][1],alo[mt][2],alo[mt][3], uAl + off);
            }
#pragma unroll
            for (int np=0; np<4; np++){
                unsigned bh0,bh1,bh2,bh3, bl0,bl1,bl2,bl3;
                unsigned off = (unsigned)(((ks + b_k)*GBP + wn*64 + np*16 + b_n)*2);
                ldsm_x4t(bh0,bh1,bh2,bh3, uBh + off);
                ldsm_x4t(bl0,bl1,bl2,bl3, uBl + off);
#pragma unroll
                for (int mt=0; mt<2; mt++){
                    mma16816(acc[mt][2*np],   ahi[mt], bh0, bh1);
                    mma16816(acc[mt][2*np],   ahi[mt], bl0, bl1);
                    mma16816(acc[mt][2*np],   alo[mt], bh0, bh1);
                    mma16816(acc[mt][2*np+1], ahi[mt], bh2, bh3);
                    mma16816(acc[mt][2*np+1], ahi[mt], bl2, bl3);
                    mma16816(acc[mt][2*np+1], alo[mt], bh2, bh3);
                }
            }
        }
        __syncthreads();
    }

#pragma unroll
    for (int mt=0; mt<2; mt++){
#pragma unroll
        for (int nt=0; nt<8; nt++){
            int col = bn + wn*64 + nt*8 + (la3<<1);
            float b0 = bias[col], b1 = bias[col+1];
            int r0 = bm + wm*32 + mt*16 + lq;
            *(float2*)&C[(size_t)r0*DM + col]     = make_float2(acc[mt][nt][0] + b0, acc[mt][nt][1] + b1);
            *(float2*)&C[(size_t)(r0+8)*DM + col] = make_float2(acc[mt][nt][2] + b0, acc[mt][nt][3] + b1);
        }
    }
}

// ======================= Fused banded attention (bf16x3) =======================
// grid (T/64, B*H), 256 threads (8 warps). Warp = 16 q-rows x 128 keys (QK^T),
// 16 q-rows x 32 d-cols (P@V). Q/K/V/P split to bf16 hi/lo in smem; fragments via
// ldmatrix. P region aliases Q; V aliases K. Writes FULL 2048-wide attn rows.
#define AQP 72    // Q pitch (bf16)
#define AKP 72    // K/V pitch (bf16)
#define APP 264   // P pitch (bf16)

// byte offsets in dynamic smem
#define O_PH 0
#define O_PL (O_PH + 64*APP*2)            // 33792
#define O_QH 0                            // aliases P (Q dies before P is written)
#define O_QL (O_QH + 64*AQP*2)            // 9216
#define O_KH (O_PL + 64*APP*2)            // 67584
#define O_KL (O_KH + 256*AKP*2)           // 104448
#define O_VH O_KH
#define O_VL O_KL
#define O_RM (O_KL + 256*AKP*2)           // 141312
#define O_RS (O_RM + 512)                 // 141824
#define A_SMEM_BYTES (O_RS + 512)         // 142336

__global__ void __launch_bounds__(256) attn_kernel(float* __restrict__ attn_out, int has_attn)
{
    extern __shared__ char smb[];
    unsigned short* Qh = (unsigned short*)(smb + O_QH);
    unsigned short* Ql = (unsigned short*)(smb + O_QL);
    unsigned short* Kh = (unsigned short*)(smb + O_KH);
    unsigned short* Kl = (unsigned short*)(smb + O_KL);
    unsigned short* Vh = (unsigned short*)(smb + O_VH);
    unsigned short* Vl = (unsigned short*)(smb + O_VL);
    unsigned short* Ph = (unsigned short*)(smb + O_PH);
    unsigned short* Pl = (unsigned short*)(smb + O_PL);
    float* Rm = (float*)(smb + O_RM);
    float* Rs = (float*)(smb + O_RS);

    const int tid = threadIdx.x, warp = tid>>5, lane = tid&31;
    const int wm = warp >> 1;        // 0..3 (16 rows each)
    const int wn = warp & 1;         // 0..1 (128 keys / 32 d-cols each)
    const int la3 = lane & 3;
    const int lq  = lane >> 2;
    const int bh = blockIdx.y;
    const int b = bh >> 4, h = bh & 15;
    const int qbase = blockIdx.x * 64;
    const int qblk  = qbase >> 7;
    const int kstart = (qblk==0) ? 0 : (qblk-1)*128;

    // ldmatrix lane offsets
    const int a_r = lane & 15;
    const int a_c = (lane >> 4) << 3;
    const int t_k = (((lane >> 3) & 1) << 3) + (lane & 7);   // for trans (V)
    const int t_n = ((lane >> 4) & 1) << 3;
    const int n_r = ((((lane >> 3) & 2) << 2)) + (lane & 7); // for non-trans B (K): quad&2 -> +8 rows
    const int n_k = (((lane >> 3) & 1) << 3);                // quad&1 -> +8 k

    const unsigned uQh = smaddr(Qh), uQl = smaddr(Ql);
    const unsigned uKh = smaddr(Kh), uKl = smaddr(Kl);
    const unsigned uVh = smaddr(Vh), uVl = smaddr(Vl);
    const unsigned uPh = smaddr(Ph), uPl = smaddr(Pl);

    // ---- load Q (64x64) and K (256x64), split to bf16 hi/lo ----
#pragma unroll
    for (int i=0;i<4;i++){
        int idx = tid + i*256;
        int r = idx >> 4, c = (idx & 15) << 2;
        float4 v = *(const float4*)&g_Q[((size_t)(b*TT + qbase + r))*DM + h*HD + c];
        unsigned h0,l0,h1,l1;
        split_bf2(v.x,v.y,h0,l0); split_bf2(v.z,v.w,h1,l1);
        *(uint2*)&Qh[r*AQP + c] = make_uint2(h0,h1);
        *(uint2*)&Ql[r*AQP + c] = make_uint2(l0,l1);
    }
#pragma unroll
    for (int i=0;i<16;i++){
        int idx = tid + i*256;
        int r = idx >> 4, c = (idx & 15) << 2;
        float4 v = *(const float4*)&g_K[((size_t)(b*TT + kstart + r))*DM + h*HD + c];
        unsigned h0,l0,h1,l1;
        split_bf2(v.x,v.y,h0,l0); split_bf2(v.z,v.w,h1,l1);
        *(uint2*)&Kh[r*AKP + c] = make_uint2(h0,h1);
        *(uint2*)&Kl[r*AKP + c] = make_uint2(l0,l1);
    }
    __syncthreads();

    // ---- S = Q K^T : warp tile 16 rows x 128 keys ----
    const int rloc0 = wm*16 + lq;
    const int rloc1 = rloc0 + 8;
    float sc[16][4];
#pragma unroll
    for (int nt=0; nt<16; nt++)
#pragma unroll
        for (int cc=0; cc<4; cc++) sc[nt][cc] = 0.f;

#pragma unroll
    for (int ks=0; ks<64; ks+=16){
        unsigned ahi[4], alo[4];
        unsigned aoff = (unsigned)(((wm*16 + a_r)*AQP + ks + a_c)*2);
        ldsm_x4(ahi[0],ahi[1],ahi[2],ahi[3], uQh + aoff);
        ldsm_x4(alo[0],alo[1],alo[2],alo[3], uQl + aoff);
#pragma unroll
        for (int np=0; np<8; np++){
            unsigned bh0,bh1,bh2,bh3, bl0,bl1,bl2,bl3;
            unsigned boff = (unsigned)(((wn*128 + np*16 + n_r)*AKP + ks + n_k)*2);
            ldsm_x4(bh0,bh1,bh2,bh3, uKh + boff);
            ldsm_x4(bl0,bl1,bl2,bl3, uKl + boff);
            mma16816(sc[2*np],   ahi, bh0, bh1);
            mma16816(sc[2*np],   ahi, bl0, bl1);
            mma16816(sc[2*np],   alo, bh0, bh1);
            mma16816(sc[2*np+1], ahi, bh2, bh3);
            mma16816(sc[2*np+1], ahi, bl2, bl3);
            mma16816(sc[2*np+1], alo, bh2, bh3);
        }
    }

    // ---- alibi + causal mask, cross-warp softmax ----
    const float slope = exp2f(-0.5f*(float)(h+1));
    const int i0 = qbase + rloc0;
    const int i1 = i0 + 8;
    float m0 = -1e30f, m1 = -1e30f;
#pragma unroll
    for (int nt=0; nt<16; nt++){
        int j = kstart + wn*128 + nt*8 + (la3<<1);
        float s;
        s = sc[nt][0]*0.125f + slope*(float)(i0 - j);
        if (j   > i0) s = -1e30f; sc[nt][0]=s; m0=fmaxf(m0,s);
        s = sc[nt][1]*0.125f + slope*(float)(i0 - j - 1);
        if (j+1 > i0) s = -1e30f; sc[nt][1]=s; m0=fmaxf(m0,s);
        s = sc[nt][2]*0.125f + slope*(float)(i1 - j);
        if (j   > i1) s = -1e30f; sc[nt][2]=s; m1=fmaxf(m1,s);
        s = sc[nt][3]*0.125f + slope*(float)(i1 - j - 1);
        if (j+1 > i1) s = -1e30f; sc[nt][3]=s; m1=fmaxf(m1,s);
    }
    m0 = fmaxf(m0, __shfl_xor_sync(0xffffffffu, m0, 1));
    m0 = fmaxf(m0, __shfl_xor_sync(0xffffffffu, m0, 2));
    m1 = fmaxf(m1, __shfl_xor_sync(0xffffffffu, m1, 1));
    m1 = fmaxf(m1, __shfl_xor_sync(0xffffffffu, m1, 2));
    if (la3 == 0){
        Rm[rloc0*2 + wn] = m0;
        Rm[rloc1*2 + wn] = m1;
    }
    __syncthreads();
    m0 = fmaxf(Rm[rloc0*2], Rm[rloc0*2 + 1]);
    m1 = fmaxf(Rm[rloc1*2], Rm[rloc1*2 + 1]);

    float l0 = 0.f, l1 = 0.f;
#pragma unroll
    for (int nt=0; nt<16; nt++){
        float p;
        p = __expf(sc[nt][0]-m0); sc[nt][0]=p; l0+=p;
        p = __expf(sc[nt][1]-m0); sc[nt][1]=p; l0+=p;
        p = __expf(sc[nt][2]-m1); sc[nt][2]=p; l1+=p;
        p = __expf(sc[nt][3]-m1); sc[nt][3]=p; l1+=p;
    }
    l0 += __shfl_xor_sync(0xffffffffu, l0, 1);
    l0 += __shfl_xor_sync(0xffffffffu, l0, 2);
    l1 += __shfl_xor_sync(0xffffffffu, l1, 1);
    l1 += __shfl_xor_sync(0xffffffffu, l1, 2);
    if (la3 == 0){
        Rs[rloc0*2 + wn] = l0;
        Rs[rloc1*2 + wn] = l1;
    }
    __syncthreads();   // all Q reads done; P may overwrite Q region after this
    const float inv0 = 1.f / (Rs[rloc0*2] + Rs[rloc0*2 + 1]);
    const float inv1 = 1.f / (Rs[rloc1*2] + Rs[rloc1*2 + 1]);

#pragma unroll
    for (int nt=0; nt<16; nt++){
        int c = wn*128 + nt*8 + (la3<<1);
        unsigned ph, pl;
        split_bf2(sc[nt][0]*inv0, sc[nt][1]*inv0, ph, pl);
        *(unsigned*)&Ph[rloc0*APP + c] = ph;
        *(unsigned*)&Pl[rloc0*APP + c] = pl;
        split_bf2(sc[nt][2]*inv1, sc[nt][3]*inv1, ph, pl);
        *(unsigned*)&Ph[rloc1*APP + c] = ph;
        *(unsigned*)&Pl[rloc1*APP + c] = pl;
    }
    __syncthreads();

    // ---- write full attn rows (band = hi+lo, rest = 0); load V (split, over K) ----
    if (has_attn){
        const float4 zero4 = make_float4(0.f,0.f,0.f,0.f);
#pragma unroll 4
        for (int i=0;i<128;i++){
            int idx = tid + i*256;             // 64 rows x 512 float4
            int r = idx >> 9;
            int c4 = (idx & 511) << 2;
            int cc = c4 - kstart;
            float4 v = zero4;
            if (cc >= 0 && cc < 256){
                __nv_bfloat162 h0 = *(__nv_bfloat162*)&Ph[r*APP + cc];
                __nv_bfloat162 h1 = *(__nv_bfloat162*)&Ph[r*APP + cc + 2];
                __nv_bfloat162 q0 = *(__nv_bfloat162*)&Pl[r*APP + cc];
                __nv_bfloat162 q1 = *(__nv_bfloat162*)&Pl[r*APP + cc + 2];
                float2 a0 = __bfloat1622float2(h0), a1 = __bfloat1622float2(h1);
                float2 b0 = __bfloat1622float2(q0), b1 = __bfloat1622float2(q1);
                v = make_float4(a0.x+b0.x, a0.y+b0.y, a1.x+b1.x, a1.y+b1.y);
            }
            *(float4*)&attn_out[((size_t)bh*TT + qbase + r)*TT + c4] = v;
        }
    }
#pragma unroll
    for (int i=0;i<16;i++){
        int idx = tid + i*256;
        int r = idx >> 4, c = (idx & 15) << 2;
        float4 v = *(const float4*)&g_V[((size_t)(b*TT + kstart + r))*DM + h*HD + c];
        unsigned h0,l0,h1,l1;
        split_bf2(v.x,v.y,h0,l0); split_bf2(v.z,v.w,h1,l1);
        *(uint2*)&Vh[r*AKP + c] = make_uint2(h0,h1);
        *(uint2*)&Vl[r*AKP + c] = make_uint2(l0,l1);
    }
    __syncthreads();

    // ---- O = P @ V : warp tile 16 rows x 32 cols ----
    float oc[4][4];
#pragma unroll
    for (int nt=0; nt<4; nt++)
#pragma unroll
        for (int cc=0; cc<4; cc++) oc[nt][cc] = 0.f;

#pragma unroll 4
    for (int ks=0; ks<256; ks+=16){
        unsigned ahi[4], alo[4];
        unsigned aoff = (unsigned)(((wm*16 + a_r)*APP + ks + a_c)*2);
        ldsm_x4(ahi[0],ahi[1],ahi[2],ahi[3], uPh + aoff);
        ldsm_x4(alo[0],alo[1],alo[2],alo[3], uPl + aoff);
#pragma unroll
        for (int np=0; np<2; np++){
            unsigned bh0,bh1,bh2,bh3, bl0,bl1,bl2,bl3;
            unsigned boff = (unsigned)(((ks + t_k)*AKP + wn*32 + np*16 + t_n)*2);
            ldsm_x4t(bh0,bh1,bh2,bh3, uVh + boff);
            ldsm_x4t(bl0,bl1,bl2,bl3, uVl + boff);
            mma16816(oc[2*np],   ahi, bh0, bh1);
            mma16816(oc[2*np],   ahi, bl0, bl1);
            mma16816(oc[2*np],   alo, bh0, bh1);
            mma16816(oc[2*np+1], ahi, bh2, bh3);
            mma16816(oc[2*np+1], ahi, bl2, bl3);
            mma16816(oc[2*np+1], alo, bh2, bh3);
        }
    }

    // ---- write O in (b*T+t, h*64+d) layout ----
#pragma unroll
    for (int nt=0; nt<4; nt++){
        int col = h*HD + wn*32 + nt*8 + (la3<<1);
        size_t rg = (size_t)(b*TT + qbase + rloc0);
        *(float2*)&g_O[ rg     *DM + col] = make_float2(oc[nt][0], oc[nt][1]);
        *(float2*)&g_O[(rg + 8)*DM + col] = make_float2(oc[nt][2], oc[nt][3]);
    }
}

// ======================= host launcher =======================
extern "C" void kernel_launch(void* const* d_in, const int* in_sizes, int n_in,
                              void* d_out, int out_size)
{
    const float* x  = (const float*)d_in[0];
    const float* Wq = (const float*)d_in[1];
    const float* bq = (const float*)d_in[2];
    const float* Wk = (const float*)d_in[3];
    const float* bk = (const float*)d_in[4];
    const float* Wv = (const float*)d_in[5];
    const float* bv = (const float*)d_in[6];
    const float* Wo = (const float*)d_in[7];
    const float* bo = (const float*)d_in[8];
    float* out = (float*)d_out;

    const long long OUT_ELEMS  = (long long)MROWS*DM;        // 4,194,304
    const long long ATTN_ELEMS = (long long)BB*NH*TT*TT;     // 134,217,728
    const int has_attn = ((long long)out_size >= OUT_ELEMS + ATTN_ELEMS) ? 1 : 0;
    float* attn = has_attn ? (out + OUT_ELEMS) : nullptr;

    float *pQ, *pK, *pV, *pO;
    cudaGetSymbolAddress((void**)&pQ, g_Q);
    cudaGetSymbolAddress((void**)&pK, g_K);
    cudaGetSymbolAddress((void**)&pV, g_V);
    cudaGetSymbolAddress((void**)&pO, g_O);

    static int attr_done = 0;
    if (!attr_done){
        cudaFuncSetAttribute(attn_kernel, cudaFuncAttributeMaxDynamicSharedMemorySize, A_SMEM_BYTES);
        attr_done = 1;
    }

    // fused Q/K/V projections
    gemm3_kernel<<<dim3(DM/128, MROWS/128, 3), 256>>>(
        x, Wq, Wk, Wv, bq, bk, bv, pQ, pK, pV);

    // banded attention (writes full attn rows: band + zeros)
    attn_kernel<<<dim3(TT/64, BB*NH), 256, A_SMEM_BYTES>>>(attn, has_attn);

    // output projection
    gemm3_kernel<<<dim3(DM/128, MROWS/128, 1), 256>>>(
        pO, Wo, Wo, Wo, bo, bo, bo, out, out, out);
}